// round 2
// baseline (speedup 1.0000x reference)
#include <cuda_runtime.h>
#include <cstdint>

// out[b,s,t] = sum_k x[b, t+k-271] * W[s,k],  B=128, T=4096, S=64, K=543.
// Packed-fp32 (fma.rn.f32x2) version: each FFMA2 does 2 FMAs (times t,t+1).

#define B_DIM   128
#define T_DIM   4096
#define S_DIM   64
#define K_DIM   543
#define K_HALF  271

#define TT      128           // time tile per block
#define KC      64            // k chunk staged in smem
#define KPAD    576           // 9*64 zero-padded K
#define NCHUNK  9
#define XS      (TT + KPAD)   // 704 staged x values

typedef unsigned long long ull;

// Pre-transposed, zero-padded, DUPLICATED bank: g_WT2[k][2s] = g_WT2[k][2s+1] = W[s][k]
__device__ float g_WT2[KPAD * S_DIM * 2];

__global__ void transpose_bank_kernel(const float* __restrict__ W) {
    int idx = blockIdx.x * blockDim.x + threadIdx.x;
    if (idx >= KPAD * S_DIM * 2) return;
    int k = idx >> 7;            // /128
    int s = (idx & 127) >> 1;    // dup pair
    g_WT2[idx] = (k < K_DIM) ? W[s * K_DIM + k] : 0.0f;
}

__device__ __forceinline__ unsigned smem_u32(const void* p) {
    unsigned a;
    asm("{ .reg .u64 t; cvta.to.shared.u64 t, %1; cvt.u32.u64 %0, t; }" : "=r"(a) : "l"(p));
    return a;
}
__device__ __forceinline__ ull lds64(unsigned a) {
    ull v; asm("ld.shared.b64 %0, [%1];" : "=l"(v) : "r"(a)); return v;
}
__device__ __forceinline__ void lds128(unsigned a, ull& x, ull& y) {
    asm("ld.shared.v2.u64 {%0,%1}, [%2];" : "=l"(x), "=l"(y) : "r"(a));
}
__device__ __forceinline__ void ffma2(ull& d, ull a, ull b) {
    asm("fma.rn.f32x2 %0, %1, %2, %0;" : "+l"(d) : "l"(a), "l"(b));
}

__global__ __launch_bounds__(128)
void ricker_cwt2_kernel(const float* __restrict__ x, float* __restrict__ out) {
    __shared__ float xsA[XS];          // xsA[i] = window value i
    __shared__ float xsB[XS];          // xsB[i] = window value i+1 (odd-k alignment shadow)
    __shared__ float ws2[KC * 128];    // per-chunk dup bank: [k][2s..2s+1]

    const int tid    = threadIdx.x;        // 0..127
    const int tile_t = blockIdx.x * TT;
    const int b      = blockIdx.y;

    const float* xrow = x + (size_t)b * T_DIM;

    // Stage x window (both aligned copies), zero-padded.
    for (int i = tid; i < XS; i += 128) {
        int g0 = tile_t + i - K_HALF;
        int g1 = g0 + 1;
        xsA[i] = (g0 >= 0 && g0 < T_DIM) ? xrow[g0] : 0.0f;
        xsB[i] = (g1 >= 0 && g1 < T_DIM) ? xrow[g1] : 0.0f;
    }

    const int tb2 = (tid & 15) * 2;        // time base: t = tb2 + 32*jp + {0,1}
    const int s0  = (tid >> 4) << 3;       // scales s0 .. s0+7

    ull acc[4][8];                          // [jp (time pair)][si (scale)]
    #pragma unroll
    for (int jp = 0; jp < 4; ++jp)
        #pragma unroll
        for (int si = 0; si < 8; ++si) acc[jp][si] = 0ULL;

    unsigned xA = smem_u32(xsA) + 4u * tb2;        // + 4*kk + 128*jp
    unsigned xB = smem_u32(xsB) + 4u * tb2;        // + 4*(kk-1) + 128*jp
    const unsigned wbase = smem_u32(ws2) + 8u * s0; // + 512*k row stride

    const float4* __restrict__ wt2 = reinterpret_cast<const float4*>(g_WT2);

    for (int c = 0; c < NCHUNK; ++c) {
        __syncthreads();
        // Stage duplicated W chunk: KC*128 floats = 2048 float4
        {
            const float4* src = wt2 + (size_t)c * (KC * 32);
            float4* dst = reinterpret_cast<float4*>(ws2);
            #pragma unroll
            for (int i = tid; i < KC * 32; i += 128) dst[i] = src[i];
        }
        __syncthreads();

        #pragma unroll 4
        for (int k2 = 0; k2 < KC; k2 += 2) {
            // ---- even k = k2 : x from xsA ----
            {
                const unsigned wrow = wbase + (unsigned)(k2 * 512);
                ull w0, w1, w2, w3, w4, w5, w6, w7;
                lds128(wrow,      w0, w1);
                lds128(wrow + 16, w2, w3);
                lds128(wrow + 32, w4, w5);
                lds128(wrow + 48, w6, w7);
                const unsigned xb = xA + (unsigned)(4 * k2);
                #pragma unroll
                for (int jp = 0; jp < 4; ++jp) {
                    const ull xp = lds64(xb + 128u * jp);
                    ffma2(acc[jp][0], xp, w0);
                    ffma2(acc[jp][1], xp, w1);
                    ffma2(acc[jp][2], xp, w2);
                    ffma2(acc[jp][3], xp, w3);
                    ffma2(acc[jp][4], xp, w4);
                    ffma2(acc[jp][5], xp, w5);
                    ffma2(acc[jp][6], xp, w6);
                    ffma2(acc[jp][7], xp, w7);
                }
            }
            // ---- odd k = k2+1 : x from xsB at index (kk-1) = k2 ----
            {
                const unsigned wrow = wbase + (unsigned)((k2 + 1) * 512);
                ull w0, w1, w2, w3, w4, w5, w6, w7;
                lds128(wrow,      w0, w1);
                lds128(wrow + 16, w2, w3);
                lds128(wrow + 32, w4, w5);
                lds128(wrow + 48, w6, w7);
                const unsigned xb = xB + (unsigned)(4 * k2);
                #pragma unroll
                for (int jp = 0; jp < 4; ++jp) {
                    const ull xp = lds64(xb + 128u * jp);
                    ffma2(acc[jp][0], xp, w0);
                    ffma2(acc[jp][1], xp, w1);
                    ffma2(acc[jp][2], xp, w2);
                    ffma2(acc[jp][3], xp, w3);
                    ffma2(acc[jp][4], xp, w4);
                    ffma2(acc[jp][5], xp, w5);
                    ffma2(acc[jp][6], xp, w6);
                    ffma2(acc[jp][7], xp, w7);
                }
            }
        }
        // advance x window by KC floats = 256 bytes
        xA += 4 * KC;
        xB += 4 * KC;
    }

    // Write out[b, s0+si, tile_t + tb2 + 32jp + {0,1}] as float2
    #pragma unroll
    for (int si = 0; si < 8; ++si) {
        float* orow = out + ((size_t)(b * S_DIM + s0 + si) * T_DIM) + tile_t + tb2;
        #pragma unroll
        for (int jp = 0; jp < 4; ++jp) {
            ull v = acc[jp][si];
            float2 f;
            asm("mov.b64 {%0,%1}, %2;" : "=f"(f.x), "=f"(f.y) : "l"(v));
            *reinterpret_cast<float2*>(orow + 32 * jp) = f;
        }
    }
}

extern "C" void kernel_launch(void* const* d_in, const int* in_sizes, int n_in,
                              void* d_out, int out_size) {
    const float* x = (const float*)d_in[0];   // [128, 4096]
    const float* W = (const float*)d_in[1];   // [64, 543]
    float* out = (float*)d_out;               // [128, 64, 4096]
    (void)in_sizes; (void)n_in; (void)out_size;

    transpose_bank_kernel<<<(KPAD * S_DIM * 2 + 255) / 256, 256>>>(W);

    dim3 grid(T_DIM / TT, B_DIM);
    ricker_cwt2_kernel<<<grid, 128>>>(x, out);
}

// round 4
// speedup vs baseline: 3.2743x; 3.2743x over previous
#include <cuda_runtime.h>
#include <cuda_bf16.h>
#include <cstdint>

// out[b,s,t] = sum_k x[b, t+k-271] * W[s,k];  B=128, T=4096, S=64, K=543.
// Warp-level bf16 mma.sync.m16n8k16 implicit GEMM (target-portable tensor path).
// 2-way bf16 split of x and W, 3 accumulating products, fp32 accumulate.

#define T_DIM   4096
#define S_DIM   64
#define K_DIM   543
#define KCH     272      // k per smem chunk (2 chunks cover 544, zero-padded)
#define WROW    280      // padded W row length (bank-conflict-free b-frags)
#define NSTEP   17       // k16 steps per chunk
#define TT      128      // t tile (M)
#define WIN     672      // x window elems: TT + 544
#define XROW    688      // padded x copy row

// smem layout (dynamic):
//   [0, 71680)           : W chunk, bf16 [2 planes(hi/lo)][64 s][280 kk]
//   [71680, 82688)       : x windows, bf16 [2 bb][2 split][2 copy][688]
//   epilogue reuses [0, 35840) as fp32 buf [64][140]
#define WS_BYTES   (2 * 64 * WROW * 2)          // 71680
#define X_OFF      WS_BYTES
#define SMEM_BYTES (WS_BYTES + 2 * 2 * 2 * XROW * 2)   // 82688
#define PLANE_B    (64 * WROW * 2)              // 35840

// Pre-split bank, chunked, padded: g_W[chunk][plane][s][kk]
__device__ uint16_t g_W[2][2][64][WROW];

__global__ void prep_bank(const float* __restrict__ W) {
    int idx = blockIdx.x * blockDim.x + threadIdx.x;
    if (idx >= 2 * 2 * 64 * WROW) return;
    int kk = idx % WROW;
    int s  = (idx / WROW) & 63;
    int p  = (idx / (WROW * 64)) & 1;
    int c  = idx / (WROW * 64 * 2);
    int k  = c * KCH + kk;
    float w = (kk < KCH && k < K_DIM) ? W[s * K_DIM + k] : 0.0f;
    __nv_bfloat16 hi = __float2bfloat16(w);
    __nv_bfloat16 lo = __float2bfloat16(w - __bfloat162float(hi));
    g_W[c][p][s][kk] = (p == 0) ? *reinterpret_cast<uint16_t*>(&hi)
                                : *reinterpret_cast<uint16_t*>(&lo);
}

__device__ __forceinline__ uint32_t smem_u32(const void* p) {
    uint32_t a;
    asm("{ .reg .u64 t; cvta.to.shared.u64 t, %1; cvt.u32.u64 %0, t; }" : "=r"(a) : "l"(p));
    return a;
}
__device__ __forceinline__ uint32_t lds32(uint32_t a) {
    uint32_t v; asm volatile("ld.shared.b32 %0, [%1];" : "=r"(v) : "r"(a)); return v;
}
__device__ __forceinline__ void mma16816(float* c, uint32_t a0, uint32_t a1,
                                         uint32_t a2, uint32_t a3,
                                         uint32_t b0, uint32_t b1) {
    asm volatile(
        "mma.sync.aligned.m16n8k16.row.col.f32.bf16.bf16.f32 "
        "{%0,%1,%2,%3}, {%4,%5,%6,%7}, {%8,%9}, {%0,%1,%2,%3};"
        : "+f"(c[0]), "+f"(c[1]), "+f"(c[2]), "+f"(c[3])
        : "r"(a0), "r"(a1), "r"(a2), "r"(a3), "r"(b0), "r"(b1));
}

extern __shared__ char smem_raw[];

__global__ __launch_bounds__(256, 2)
void cwt_mma_kernel(const float* __restrict__ x, float* __restrict__ out) {
    uint16_t* Wsm  = reinterpret_cast<uint16_t*>(smem_raw);
    uint16_t* Xsm  = reinterpret_cast<uint16_t*>(smem_raw + X_OFF);
    float*    Obuf = reinterpret_cast<float*>(smem_raw);   // epilogue reuse

    const int tid  = threadIdx.x;
    const int wid  = tid >> 5;
    const int lane = tid & 31;
    const int t0   = blockIdx.x * TT;
    const int bp   = blockIdx.y;          // batch pair index

    // ---- stage x windows: bf16 hi/lo, plus 1-element-shifted copies ----
    for (int bb = 0; bb < 2; ++bb) {
        const float* xr = x + (size_t)(bp * 2 + bb) * T_DIM;
        uint16_t* ph = Xsm + (bb * 2 + 0) * 2 * XROW;  // [split=hi][copy]
        uint16_t* pl = Xsm + (bb * 2 + 1) * 2 * XROW;
        for (int i = tid; i < WIN; i += 256) {
            int g = t0 + i - 271;
            float v = (g >= 0 && g < T_DIM) ? xr[g] : 0.0f;
            __nv_bfloat16 h = __float2bfloat16(v);
            __nv_bfloat16 l = __float2bfloat16(v - __bfloat162float(h));
            uint16_t hb = *reinterpret_cast<uint16_t*>(&h);
            uint16_t lb = *reinterpret_cast<uint16_t*>(&l);
            ph[i] = hb; pl[i] = lb;
            if (i) { ph[XROW + i - 1] = hb; pl[XROW + i - 1] = lb; }
        }
    }

    // ---- per-thread fragment base addresses ----
    const int g   = lane >> 2;       // group id (row within tile)
    const int q   = lane & 3;        // thread-in-group
    const int podd = g & 1;          // parity of a-pair element index
    // a-frag base element (4B aligned by parity-shifted copy selection)
    const int eb = 16 * wid + g + 2 * q - podd;
    uint32_t xa[2][2];
    #pragma unroll
    for (int bb = 0; bb < 2; ++bb)
        #pragma unroll
        for (int sp = 0; sp < 2; ++sp)
            xa[bb][sp] = smem_u32(Xsm) +
                (uint32_t)((((bb * 2 + sp) * 2 + podd) * XROW + eb) * 2);

    // b-frag base: W[s = 8j + g][k = 2q] within chunk, plane hi
    const uint32_t wb0 = smem_u32(Wsm) + (uint32_t)((g * WROW + 2 * q) * 2);

    float acc[2][8][4];
    #pragma unroll
    for (int bb = 0; bb < 2; ++bb)
        #pragma unroll
        for (int j = 0; j < 8; ++j)
            #pragma unroll
            for (int r = 0; r < 4; ++r) acc[bb][j][r] = 0.0f;

    for (int ch = 0; ch < 2; ++ch) {
        __syncthreads();
        // stage W chunk (both planes contiguous, 71680 B)
        {
            const int4* src = reinterpret_cast<const int4*>(&g_W[ch][0][0][0]);
            int4* dst = reinterpret_cast<int4*>(Wsm);
            for (int i = tid; i < WS_BYTES / 16; i += 256) dst[i] = src[i];
        }
        __syncthreads();

        const uint32_t xko = (uint32_t)(ch * KCH * 2);   // global k byte offset
        #pragma unroll 1
        for (int st = 0; st < NSTEP; ++st) {
            // load b-fragments for all 8 n-tiles, hi+lo planes
            uint32_t wh[8][2], wl[8][2];
            const uint32_t wstep = wb0 + (uint32_t)(st * 32);
            #pragma unroll
            for (int j = 0; j < 8; ++j) {
                uint32_t a = wstep + (uint32_t)(j * (WROW * 8 * 2));
                wh[j][0] = lds32(a);
                wh[j][1] = lds32(a + 16);
                wl[j][0] = lds32(a + PLANE_B);
                wl[j][1] = lds32(a + PLANE_B + 16);
            }
            const uint32_t xoff = xko + (uint32_t)(st * 32);
            #pragma unroll
            for (int bb = 0; bb < 2; ++bb) {
                // a-fragments (Hankel: a1 == a2)
                const uint32_t bh = xa[bb][0] + xoff;
                const uint32_t bl = xa[bb][1] + xoff;
                uint32_t ah0 = lds32(bh), ah1 = lds32(bh + 16), ah3 = lds32(bh + 32);
                uint32_t al0 = lds32(bl), al1 = lds32(bl + 16), al3 = lds32(bl + 32);
                #pragma unroll
                for (int j = 0; j < 8; ++j) {
                    mma16816(acc[bb][j], ah0, ah1, ah1, ah3, wh[j][0], wh[j][1]);
                    mma16816(acc[bb][j], ah0, ah1, ah1, ah3, wl[j][0], wl[j][1]);
                    mma16816(acc[bb][j], al0, al1, al1, al3, wh[j][0], wh[j][1]);
                }
            }
        }
    }

    // ---- epilogue: transpose through smem, coalesced stores ----
    for (int bb = 0; bb < 2; ++bb) {
        __syncthreads();   // Wsm/Obuf free (and prior reads done)
        const int tloc = 16 * wid + g;
        #pragma unroll
        for (int j = 0; j < 8; ++j) {
            const int s = 8 * j + 2 * q;
            Obuf[s * 140 + tloc]           = acc[bb][j][0];
            Obuf[(s + 1) * 140 + tloc]     = acc[bb][j][1];
            Obuf[s * 140 + tloc + 8]       = acc[bb][j][2];
            Obuf[(s + 1) * 140 + tloc + 8] = acc[bb][j][3];
        }
        __syncthreads();
        const size_t ob = ((size_t)((bp * 2 + bb) * S_DIM)) * T_DIM + t0;
        for (int i = tid; i < 2048; i += 256) {
            const int s = i >> 5, tq = i & 31;
            float4 v = *reinterpret_cast<float4*>(&Obuf[s * 140 + 4 * tq]);
            *reinterpret_cast<float4*>(&out[ob + (size_t)s * T_DIM + 4 * tq]) = v;
        }
    }
}

extern "C" void kernel_launch(void* const* d_in, const int* in_sizes, int n_in,
                              void* d_out, int out_size) {
    const float* x = (const float*)d_in[0];   // [128, 4096]
    const float* W = (const float*)d_in[1];   // [64, 543]
    float* out = (float*)d_out;               // [128, 64, 4096]
    (void)in_sizes; (void)n_in; (void)out_size;

    prep_bank<<<(2 * 2 * 64 * WROW + 255) / 256, 256>>>(W);

    cudaFuncSetAttribute(cwt_mma_kernel,
                         cudaFuncAttributeMaxDynamicSharedMemorySize, SMEM_BYTES);
    dim3 grid(T_DIM / TT, 64);                // (32, 64) — 2 batches per CTA
    cwt_mma_kernel<<<grid, 256, SMEM_BYTES>>>(x, out);
}

// round 5
// speedup vs baseline: 7.1819x; 2.1935x over previous
#include <cuda_runtime.h>
#include <cuda_fp16.h>
#include <cstdint>

// out[b,s,t] = sum_k x[b, t+k-271] * W[s,k];  B=128, T=4096, S=64, K=543.
// Warp-level fp16 mma.sync.m16n8k16 implicit GEMM, SINGLE pass (fp16 inputs,
// fp32 accumulate). Error ~2^-12 per term -> norm rel_err ~3e-4 < 1e-3.

#define T_DIM   4096
#define S_DIM   64
#define K_DIM   543
#define KPAD    544      // 34 * 16
#define NSTEP   34
#define WROW    552      // padded W row (conflict-free b-frag LDS)
#define TT      128      // t tile (M)
#define WIN     672      // x window: TT + KPAD
#define XROW    688      // padded x copy row (elems)

// smem: [0, 70656) W fp16 [64 s][552 kk]; [70656, 76160) x fp16 [2 bb][2 copy][688]
// epilogue reuses [0, 35840) as f32 Obuf[64][140]
#define WS_BYTES   (64 * WROW * 2)                     // 70656
#define X_OFF      WS_BYTES
#define SMEM_BYTES (WS_BYTES + 2 * 2 * XROW * 2)       // 76160

__device__ uint16_t g_W[64][WROW];     // fp16, zero-padded

__global__ void prep_bank(const float* __restrict__ W) {
    int idx = blockIdx.x * blockDim.x + threadIdx.x;
    if (idx >= 64 * WROW) return;
    int s  = idx / WROW;
    int kk = idx % WROW;
    float w = (kk < K_DIM) ? W[s * K_DIM + kk] : 0.0f;
    __half h = __float2half_rn(w);
    g_W[s][kk] = *reinterpret_cast<uint16_t*>(&h);
}

__device__ __forceinline__ uint32_t smem_u32(const void* p) {
    uint32_t a;
    asm("{ .reg .u64 t; cvta.to.shared.u64 t, %1; cvt.u32.u64 %0, t; }" : "=r"(a) : "l"(p));
    return a;
}
__device__ __forceinline__ uint32_t lds32(uint32_t a) {
    uint32_t v; asm volatile("ld.shared.b32 %0, [%1];" : "=r"(v) : "r"(a)); return v;
}
__device__ __forceinline__ void mma16816(float* c, uint32_t a0, uint32_t a1,
                                         uint32_t a2, uint32_t a3,
                                         uint32_t b0, uint32_t b1) {
    asm volatile(
        "mma.sync.aligned.m16n8k16.row.col.f32.f16.f16.f32 "
        "{%0,%1,%2,%3}, {%4,%5,%6,%7}, {%8,%9}, {%0,%1,%2,%3};"
        : "+f"(c[0]), "+f"(c[1]), "+f"(c[2]), "+f"(c[3])
        : "r"(a0), "r"(a1), "r"(a2), "r"(a3), "r"(b0), "r"(b1));
}

extern __shared__ char smem_raw[];

__global__ __launch_bounds__(256, 2)
void cwt_mma_kernel(const float* __restrict__ x, float* __restrict__ out) {
    uint16_t* Wsm  = reinterpret_cast<uint16_t*>(smem_raw);
    uint16_t* Xsm  = reinterpret_cast<uint16_t*>(smem_raw + X_OFF);
    float*    Obuf = reinterpret_cast<float*>(smem_raw);   // epilogue reuse

    const int tid  = threadIdx.x;
    const int wid  = tid >> 5;
    const int lane = tid & 31;
    const int t0   = blockIdx.x * TT;
    const int bp   = blockIdx.y;          // batch pair

    // ---- stage W (entire padded bank, fp16) ----
    {
        const int4* src = reinterpret_cast<const int4*>(&g_W[0][0]);
        int4* dst = reinterpret_cast<int4*>(Wsm);
        for (int i = tid; i < WS_BYTES / 16; i += 256) dst[i] = src[i];
    }

    // ---- stage x windows: fp16, plus 1-element-shifted copy ----
    for (int bb = 0; bb < 2; ++bb) {
        const float* xr = x + (size_t)(bp * 2 + bb) * T_DIM;
        uint16_t* p = Xsm + bb * 2 * XROW;
        for (int i = tid; i < WIN; i += 256) {
            int g = t0 + i - 271;
            float v = (g >= 0 && g < T_DIM) ? xr[g] : 0.0f;
            __half h = __float2half_rn(v);
            uint16_t hb = *reinterpret_cast<uint16_t*>(&h);
            p[i] = hb;
            if (i) p[XROW + i - 1] = hb;
        }
    }
    __syncthreads();

    // ---- per-thread fragment addresses ----
    const int g    = lane >> 2;       // row-in-tile group
    const int q    = lane & 3;        // thread-in-group
    const int podd = g & 1;           // parity -> shifted-copy select
    const int eb   = 16 * wid + g + 2 * q - podd;    // 4B-aligned element base
    uint32_t xa[2];
    #pragma unroll
    for (int bb = 0; bb < 2; ++bb)
        xa[bb] = smem_u32(Xsm) + (uint32_t)(((bb * 2 + podd) * XROW + eb) * 2);

    // b-frag base: W[s = 8j + g][k = 2q]
    const uint32_t wb0 = smem_u32(Wsm) + (uint32_t)((g * WROW + 2 * q) * 2);

    float acc[2][8][4];
    #pragma unroll
    for (int bb = 0; bb < 2; ++bb)
        #pragma unroll
        for (int j = 0; j < 8; ++j)
            #pragma unroll
            for (int r = 0; r < 4; ++r) acc[bb][j][r] = 0.0f;

    #pragma unroll 2
    for (int st = 0; st < NSTEP; ++st) {
        uint32_t wf[8][2];
        const uint32_t wstep = wb0 + (uint32_t)(st * 32);
        #pragma unroll
        for (int j = 0; j < 8; ++j) {
            uint32_t a = wstep + (uint32_t)(j * (WROW * 8 * 2));
            wf[j][0] = lds32(a);
            wf[j][1] = lds32(a + 16);
        }
        #pragma unroll
        for (int bb = 0; bb < 2; ++bb) {
            const uint32_t bh = xa[bb] + (uint32_t)(st * 32);
            uint32_t a0 = lds32(bh), a1 = lds32(bh + 16), a3 = lds32(bh + 32);
            #pragma unroll
            for (int j = 0; j < 8; ++j)
                mma16816(acc[bb][j], a0, a1, a1, a3, wf[j][0], wf[j][1]);
        }
    }

    // ---- epilogue: transpose via smem, coalesced float4 stores ----
    for (int bb = 0; bb < 2; ++bb) {
        __syncthreads();
        const int tloc = 16 * wid + g;
        #pragma unroll
        for (int j = 0; j < 8; ++j) {
            const int s = 8 * j + 2 * q;
            Obuf[s * 140 + tloc]           = acc[bb][j][0];
            Obuf[(s + 1) * 140 + tloc]     = acc[bb][j][1];
            Obuf[s * 140 + tloc + 8]       = acc[bb][j][2];
            Obuf[(s + 1) * 140 + tloc + 8] = acc[bb][j][3];
        }
        __syncthreads();
        const size_t ob = ((size_t)((bp * 2 + bb) * S_DIM)) * T_DIM + t0;
        for (int i = tid; i < 2048; i += 256) {
            const int s = i >> 5, tq = i & 31;
            float4 v = *reinterpret_cast<float4*>(&Obuf[s * 140 + 4 * tq]);
            *reinterpret_cast<float4*>(&out[ob + (size_t)s * T_DIM + 4 * tq]) = v;
        }
    }
}

extern "C" void kernel_launch(void* const* d_in, const int* in_sizes, int n_in,
                              void* d_out, int out_size) {
    const float* x = (const float*)d_in[0];   // [128, 4096]
    const float* W = (const float*)d_in[1];   // [64, 543]
    float* out = (float*)d_out;               // [128, 64, 4096]
    (void)in_sizes; (void)n_in; (void)out_size;

    prep_bank<<<(64 * WROW + 255) / 256, 256>>>(W);

    cudaFuncSetAttribute(cwt_mma_kernel,
                         cudaFuncAttributeMaxDynamicSharedMemorySize, SMEM_BYTES);
    dim3 grid(T_DIM / TT, 64);                // 2 batches per CTA
    cwt_mma_kernel<<<grid, 256, SMEM_BYTES>>>(x, out);
}